// round 2
// baseline (speedup 1.0000x reference)
#include <cuda_runtime.h>
#include <cstdint>

// Problem constants (shapes fixed by the dataset)
#define NN 500000
#define EE 4000000
#define GG 16384
#define XD 64
#define ED 16
#define INNER 512
#define DEPTH 4

// ---------------- scratch (static device allocations; no cudaMalloc) -------
__device__ float g_x0[(size_t)NN * XD];
__device__ float g_x1[(size_t)NN * XD];
__device__ float g_aggE[(size_t)NN * ED];
__device__ float g_fp[(size_t)GG * INNER];

// ---------------- helpers ----------------
__device__ __forceinline__ float4 ld4(const float* p) {
    return *reinterpret_cast<const float4*>(p);
}
__device__ __forceinline__ void red_add_v4(float* p, float4 v) {
    asm volatile("red.global.add.v4.f32 [%0], {%1,%2,%3,%4};"
                 :: "l"(p), "f"(v.x), "f"(v.y), "f"(v.z), "f"(v.w) : "memory");
}

// ============================================================================
// Kernel A: fused  logits = x @ W_out^T + b ; softmax ; fp[batch[n]] += p
// Tile: 32 nodes x 512 cols, K=64.  256 threads, 4x4 micro-tiles.
// smem: ls[32][516] logits (padded), xs[64][32] (x^T), ws[64][128] (W^T chunk)
// ============================================================================
#define MT 32
#define LSP 516  // padded row of ls (512+4) -> conflict-free stores

__global__ void __launch_bounds__(256, 2)
kernelA(const float* __restrict__ x, const float* __restrict__ W,
        const float* __restrict__ bias, const int* __restrict__ batch,
        float* __restrict__ fp, int nNodes)
{
    extern __shared__ float sm[];
    float* ls = sm;                    // 32*516
    float* xs = ls + MT * LSP;         // 64*32   xs[k*32+m]
    float* ws = xs + 64 * MT;          // 64*128  ws[k*128+n]
    __shared__ float scale[MT];
    __shared__ int   bs[MT];

    const int tid  = threadIdx.x;
    const int base = blockIdx.x * MT;
    const int valid = min(MT, nNodes - base);

    // load x tile transposed: 32 nodes x 16 float4
    for (int i = tid; i < MT * 16; i += 256) {
        int m = i & 31, kq = i >> 5;
        float4 v = (m < valid) ? ld4(&x[(size_t)(base + m) * XD + kq * 4])
                               : make_float4(0.f, 0.f, 0.f, 0.f);
        xs[(kq * 4 + 0) * MT + m] = v.x;
        xs[(kq * 4 + 1) * MT + m] = v.y;
        xs[(kq * 4 + 2) * MT + m] = v.z;
        xs[(kq * 4 + 3) * MT + m] = v.w;
    }
    if (tid < MT) bs[tid] = (tid < valid) ? batch[base + tid] : -1;

    const int tm = tid & 7;    // 8 m-groups (4 nodes each)
    const int tn = tid >> 3;   // 32 n-groups (4 cols each)

    for (int pass = 0; pass < 4; ++pass) {
        __syncthreads();  // xs/bs ready (pass0) / prev pass done reading ws
        // load W chunk transposed: 128 rows x 16 float4
        for (int i = tid; i < 128 * 16; i += 256) {
            int n = i & 127, kq = i >> 7;
            float4 v = ld4(&W[(size_t)(pass * 128 + n) * XD + kq * 4]);
            ws[(kq * 4 + 0) * 128 + n] = v.x;
            ws[(kq * 4 + 1) * 128 + n] = v.y;
            ws[(kq * 4 + 2) * 128 + n] = v.z;
            ws[(kq * 4 + 3) * 128 + n] = v.w;
        }
        __syncthreads();

        const int nb = pass * 128 + tn * 4;
        float b0 = bias[nb + 0], b1 = bias[nb + 1], b2 = bias[nb + 2], b3 = bias[nb + 3];
        float acc[4][4];
        #pragma unroll
        for (int i = 0; i < 4; ++i) {
            acc[i][0] = b0; acc[i][1] = b1; acc[i][2] = b2; acc[i][3] = b3;
        }
        #pragma unroll
        for (int k = 0; k < 64; ++k) {
            float4 a = *reinterpret_cast<float4*>(&xs[k * MT + tm * 4]);
            float4 w = *reinterpret_cast<float4*>(&ws[k * 128 + tn * 4]);
            acc[0][0] += a.x * w.x; acc[0][1] += a.x * w.y; acc[0][2] += a.x * w.z; acc[0][3] += a.x * w.w;
            acc[1][0] += a.y * w.x; acc[1][1] += a.y * w.y; acc[1][2] += a.y * w.z; acc[1][3] += a.y * w.w;
            acc[2][0] += a.z * w.x; acc[2][1] += a.z * w.y; acc[2][2] += a.z * w.z; acc[2][3] += a.z * w.w;
            acc[3][0] += a.w * w.x; acc[3][1] += a.w * w.y; acc[3][2] += a.w * w.z; acc[3][3] += a.w * w.w;
        }
        #pragma unroll
        for (int i = 0; i < 4; ++i) {
            float4 v = make_float4(acc[i][0], acc[i][1], acc[i][2], acc[i][3]);
            *reinterpret_cast<float4*>(&ls[(tm * 4 + i) * LSP + nb]) = v;
        }
    }
    __syncthreads();

    // softmax: 8 threads per node
    {
        const int m = tid >> 3, l8 = tid & 7;
        float mx = -1e30f;
        for (int c = l8; c < INNER; c += 8) mx = fmaxf(mx, ls[m * LSP + c]);
        mx = fmaxf(mx, __shfl_xor_sync(0xffffffffu, mx, 1));
        mx = fmaxf(mx, __shfl_xor_sync(0xffffffffu, mx, 2));
        mx = fmaxf(mx, __shfl_xor_sync(0xffffffffu, mx, 4));
        float s = 0.f;
        for (int c = l8; c < INNER; c += 8) {
            float e = __expf(ls[m * LSP + c] - mx);
            ls[m * LSP + c] = e;
            s += e;
        }
        s += __shfl_xor_sync(0xffffffffu, s, 1);
        s += __shfl_xor_sync(0xffffffffu, s, 2);
        s += __shfl_xor_sync(0xffffffffu, s, 4);
        if (l8 == 0) scale[m] = (m < valid) ? 1.f / s : 0.f;
    }
    __syncthreads();

    // segment-sum into fp (batch is sorted -> run-flush)
    #pragma unroll
    for (int c0 = 0; c0 < 2; ++c0) {
        int c = tid + c0 * 256;
        float acc = 0.f;
        int prev = bs[0];
        for (int m = 0; m < valid; ++m) {
            int bb = bs[m];
            if (bb != prev) {
                atomicAdd(&fp[(size_t)prev * INNER + c], acc);
                acc = 0.f;
                prev = bb;
            }
            acc += ls[m * LSP + c] * scale[m];
        }
        if (valid > 0) atomicAdd(&fp[(size_t)prev * INNER + c], acc);
    }
}

// ============================================================================
// Edge scatter: xB[dst] += x[src] (vec4 atomics), aggE[dst] += edge_attr[e]
// 16 lanes per edge, one float4 each.
// ============================================================================
__global__ void scatterK(const float* __restrict__ x,
                         const float* __restrict__ ea,
                         const int* __restrict__ ei,
                         float* __restrict__ xB, float* __restrict__ aggE,
                         int nEdges)
{
    long long gid = (long long)blockIdx.x * blockDim.x + threadIdx.x;
    int e = (int)(gid >> 4);
    int c = (int)(gid & 15);
    if (e >= nEdges) return;
    int src = __ldg(&ei[e]);
    int dst = __ldg(&ei[nEdges + e]);
    float4 g = ld4(&x[(size_t)src * XD + c * 4]);
    red_add_v4(&xB[(size_t)dst * XD + c * 4], g);
    if (c < 4) {
        float4 a = ld4(&ea[(size_t)e * ED + c * 4]);
        red_add_v4(&aggE[(size_t)dst * ED + c * 4], a);
    }
}

// ============================================================================
// Conv linear: x_new[n] = W_in @ concat(agg_x[n], agg_e[n]) + b  (in-place on xB)
// 256 threads = 4 node-lanes x 64 outputs; 16 nodes per block.
// ============================================================================
__global__ void __launch_bounds__(256)
convLinear(float* __restrict__ xB, const float* __restrict__ aggE,
           const float* __restrict__ Wi, const float* __restrict__ bi, int nNodes)
{
    __shared__ float Wt[80 * 64];   // Wt[k*64+out]
    __shared__ float ax[4][80];
    const int tid = threadIdx.x;
    for (int i = tid; i < 64 * 80; i += 256) {
        int out = i / 80, k = i % 80;
        Wt[k * 64 + out] = Wi[i];
    }
    const int out = tid & 63, ng = tid >> 6;
    const int base = blockIdx.x * 16;
    for (int it = 0; it < 4; ++it) {
        int node = base + it * 4 + ng;
        __syncthreads();
        if (node < nNodes) {
            ax[ng][out] = xB[(size_t)node * XD + out];
            if (out < ED) ax[ng][64 + out] = aggE[(size_t)node * ED + out];
        }
        __syncthreads();
        if (node < nNodes) {
            float acc = bi[out];
            #pragma unroll
            for (int k = 0; k < 64; ++k) acc += Wt[k * 64 + out] * ax[ng][k];
            #pragma unroll
            for (int k = 0; k < 16; ++k) acc += Wt[(64 + k) * 64 + out] * ax[ng][64 + k];
            xB[(size_t)node * XD + out] = acc;
        }
    }
}

// ============================================================================
// Final MLP: out[g] = sigmoid( (fp[g] @ lin1^T + b1) @ lin2^T + b2 )
// One warp per graph; fp row cached in 16 registers per lane.
// ============================================================================
__global__ void finalK(const float* __restrict__ fp,
                       const float* __restrict__ l1w, const float* __restrict__ l1b,
                       const float* __restrict__ l2w, const float* __restrict__ l2b,
                       float* __restrict__ out, int nG)
{
    int warp = (int)((blockIdx.x * (long long)blockDim.x + threadIdx.x) >> 5);
    int lane = threadIdx.x & 31;
    if (warp >= nG) return;
    float f[16];
    #pragma unroll
    for (int j = 0; j < 16; ++j) f[j] = fp[(size_t)warp * INNER + lane + j * 32];
    float o2 = 0.f;
    for (int o = 0; o < 50; ++o) {
        float a = 0.f;
        #pragma unroll
        for (int j = 0; j < 16; ++j)
            a += f[j] * __ldg(&l1w[(size_t)o * INNER + lane + j * 32]);
        a += __shfl_xor_sync(0xffffffffu, a, 16);
        a += __shfl_xor_sync(0xffffffffu, a, 8);
        a += __shfl_xor_sync(0xffffffffu, a, 4);
        a += __shfl_xor_sync(0xffffffffu, a, 2);
        a += __shfl_xor_sync(0xffffffffu, a, 1);
        if (lane == 0) o2 += (a + l1b[o]) * l2w[o];
    }
    if (lane == 0) {
        float z = o2 + l2b[0];
        out[warp] = 1.f / (1.f + __expf(-z));
    }
}

// ============================================================================
// Host orchestration (graph-capturable: kernels + async memcpy/memset only)
// ============================================================================
extern "C" void kernel_launch(void* const* d_in, const int* in_sizes, int n_in,
                              void* d_out, int out_size)
{
    const float* x_in  = (const float*)d_in[0];
    const float* eattr = (const float*)d_in[1];
    const float* Winw  = (const float*)d_in[2];
    const float* Winb  = (const float*)d_in[3];
    const float* Woutw = (const float*)d_in[4];
    const float* Woutb = (const float*)d_in[5];
    const float* l1w   = (const float*)d_in[6];
    const float* l1b   = (const float*)d_in[7];
    const float* l2w   = (const float*)d_in[8];
    const float* l2b   = (const float*)d_in[9];
    const int*   ei    = (const int*)d_in[10];
    const int*   batch = (const int*)d_in[11];

    const int nNodes = in_sizes[0] / XD;
    const int nEdges = in_sizes[1] / ED;
    const int nG     = out_size;

    float *x0, *x1, *aggE, *fp;
    cudaGetSymbolAddress((void**)&x0,   g_x0);
    cudaGetSymbolAddress((void**)&x1,   g_x1);
    cudaGetSymbolAddress((void**)&aggE, g_aggE);
    cudaGetSymbolAddress((void**)&fp,   g_fp);

    const int smemA = (MT * LSP + 64 * MT + 64 * 128) * (int)sizeof(float); // 107008
    cudaFuncSetAttribute(kernelA, cudaFuncAttributeMaxDynamicSharedMemorySize, smemA);

    cudaMemsetAsync(fp, 0, (size_t)nG * INNER * sizeof(float));

    const int gridA    = (nNodes + MT - 1) / MT;
    const int gridScat = (int)(((long long)nEdges * 16 + 255) / 256);
    const int gridConv = (nNodes + 15) / 16;

    const float* cur = x_in;
    float* bufs[2] = { x0, x1 };
    int pb = 0;

    for (int i = 0; i <= DEPTH; ++i) {
        kernelA<<<gridA, 256, smemA>>>(cur, Woutw, Woutb, batch, fp, nNodes);
        if (i < DEPTH) {
            float* nxt = bufs[pb];
            cudaMemcpyAsync(nxt, cur, (size_t)nNodes * XD * sizeof(float),
                            cudaMemcpyDeviceToDevice);
            cudaMemsetAsync(aggE, 0, (size_t)nNodes * ED * sizeof(float));
            scatterK<<<gridScat, 256>>>(cur, eattr, ei, nxt, aggE, nEdges);
            convLinear<<<gridConv, 256>>>(nxt, aggE, Winw, Winb, nNodes);
            cur = nxt;
            pb ^= 1;
        }
    }

    finalK<<<(nG * 32 + 255) / 256, 256>>>(fp, l1w, l1b, l2w, l2b,
                                           (float*)d_out, nG);
}

// round 4
// speedup vs baseline: 1.3887x; 1.3887x over previous
#include <cuda_runtime.h>
#include <cstdint>

// Problem constants (shapes fixed by the dataset)
#define NN 500000
#define EE 4000000
#define GG 16384
#define XD 64
#define ED 16
#define INNER 512
#define DEPTH 4

#define FULLMASK 0xffffffffu

// ---------------- scratch (static device allocations; no cudaMalloc) -------
__device__ float g_x0[(size_t)NN * XD];
__device__ float g_x1[(size_t)NN * XD];
__device__ float g_aggE[(size_t)NN * ED];
__device__ float g_fp[(size_t)GG * INNER];

// ---------------- helpers ----------------
__device__ __forceinline__ float4 ld4(const float* p) {
    return *reinterpret_cast<const float4*>(p);
}
__device__ __forceinline__ void red_add_v4(float* p, float4 v) {
    asm volatile("red.global.add.v4.f32 [%0], {%1,%2,%3,%4};"
                 :: "l"(p), "f"(v.x), "f"(v.y), "f"(v.z), "f"(v.w) : "memory");
}
__device__ __forceinline__ float to_tf32(float f) {
    uint32_t o;
    asm("cvt.rna.tf32.f32 %0, %1;" : "=r"(o) : "f"(f));
    return __uint_as_float(o);
}

// ============================================================================
// kernelAmma: tf32 mma.sync GEMM (logits = x @ W_out^T + b), fused
// softmax (no-max, clamped) + sorted-batch segment-sum into fp.
//
// Tile: 64 nodes x 512 cols, K=64. 256 threads = 8 warps
//   warp = (mtile in 0..3 [16 rows each]) x (half in 0..1 [64 of 128 pass cols])
// W is staged per 128-col pass into smem [128][68] (padded, conflict-free).
// x tile staged once into smem [64][68]; A fragments held in 32 regs.
// Epilogue fused into MMA: exp(d + bias), row-sum in regs, ls written once.
// ============================================================================
#define MT 64
#define LSP 516
#define XP 68

__global__ void __launch_bounds__(256, 1)
kernelAmma(const float* __restrict__ x, const float* __restrict__ W,
           const float* __restrict__ bias, const int* __restrict__ batch,
           float* __restrict__ fp, int nNodes)
{
    extern __shared__ char dsm[];
    float* xs = (float*)dsm;              // 64 * 68
    float* Wc = xs + MT * XP;             // 128 * 68
    float* ls = Wc + 128 * XP;            // 64 * 516
    __shared__ float sbias[INNER];
    __shared__ float ssum[2][MT];
    __shared__ float sscale[MT];
    __shared__ int   sbatch[MT];

    const int tid  = threadIdx.x;
    const int w    = tid >> 5, lane = tid & 31;
    const int gid  = lane >> 2, tq = lane & 3;   // mma group / thread-in-group
    const int base = blockIdx.x * MT;
    const int valid = min(MT, nNodes - base);

    for (int i = tid; i < INNER; i += 256) sbias[i] = bias[i];
    if (tid < MT) sbatch[tid] = (tid < valid) ? batch[base + tid] : -1;

    // stage x tile (tf32-rounded): 64 rows x 16 float4
    for (int i = tid; i < MT * 16; i += 256) {
        int r = i >> 4, kq = i & 15;
        float4 v = (r < valid) ? ld4(&x[(size_t)(base + r) * XD + kq * 4])
                               : make_float4(0.f, 0.f, 0.f, 0.f);
        v.x = to_tf32(v.x); v.y = to_tf32(v.y); v.z = to_tf32(v.z); v.w = to_tf32(v.w);
        *(float4*)&xs[r * XP + kq * 4] = v;
    }
    __syncthreads();

    const int mt = w & 3, half = w >> 2;
    const int m0 = mt * 16;

    // A fragments (per-warp, reused across all 4 passes): 8 k-steps x 4 regs
    uint32_t A[8][4];
    {
        const uint32_t* xr = (const uint32_t*)xs;
        #pragma unroll
        for (int ks = 0; ks < 8; ++ks) {
            int c0 = ks * 8 + tq;
            A[ks][0] = xr[(m0 + gid) * XP + c0];
            A[ks][1] = xr[(m0 + gid + 8) * XP + c0];
            A[ks][2] = xr[(m0 + gid) * XP + c0 + 4];
            A[ks][3] = xr[(m0 + gid + 8) * XP + c0 + 4];
        }
    }

    float rs0 = 0.f, rs1 = 0.f;   // row sums for rows m0+gid and m0+gid+8

    for (int p = 0; p < 4; ++p) {
        __syncthreads();   // prior pass done reading Wc
        // stage W rows [p*128, p*128+128) x 64 cols (tf32-rounded)
        for (int i = tid; i < 128 * 16; i += 256) {
            int n = i >> 4, kq = i & 15;
            float4 v = ld4(&W[(size_t)(p * 128 + n) * XD + kq * 4]);
            v.x = to_tf32(v.x); v.y = to_tf32(v.y); v.z = to_tf32(v.z); v.w = to_tf32(v.w);
            *(float4*)&Wc[n * XP + kq * 4] = v;
        }
        __syncthreads();

        const int cb = p * 128 + half * 64;
        const uint32_t* wr = (const uint32_t*)Wc;

        #pragma unroll
        for (int nt = 0; nt < 8; ++nt) {
            const int nloc = half * 64 + nt * 8 + gid;
            float d0 = 0.f, d1 = 0.f, d2 = 0.f, d3 = 0.f;
            #pragma unroll
            for (int ks = 0; ks < 8; ++ks) {
                uint32_t b0 = wr[nloc * XP + ks * 8 + tq];
                uint32_t b1 = wr[nloc * XP + ks * 8 + tq + 4];
                asm volatile(
                    "mma.sync.aligned.m16n8k8.row.col.f32.tf32.tf32.f32 "
                    "{%0,%1,%2,%3}, {%4,%5,%6,%7}, {%8,%9}, {%0,%1,%2,%3};"
                    : "+f"(d0), "+f"(d1), "+f"(d2), "+f"(d3)
                    : "r"(A[ks][0]), "r"(A[ks][1]), "r"(A[ks][2]), "r"(A[ks][3]),
                      "r"(b0), "r"(b1));
            }
            // fused epilogue: +bias, exp (clamped), row-sum, store once
            const int c = cb + nt * 8 + tq * 2;
            float e0 = __expf(fminf(d0 + sbias[c],     85.f));
            float e1 = __expf(fminf(d1 + sbias[c + 1], 85.f));
            float e2 = __expf(fminf(d2 + sbias[c],     85.f));
            float e3 = __expf(fminf(d3 + sbias[c + 1], 85.f));
            rs0 += e0 + e1;
            rs1 += e2 + e3;
            const int r0 = m0 + gid, r1 = r0 + 8;
            *(float2*)&ls[r0 * LSP + c] = make_float2(e0, e1);
            *(float2*)&ls[r1 * LSP + c] = make_float2(e2, e3);
        }
    }

    // reduce row sums across the 4-thread quad (lanes share rows)
    rs0 += __shfl_xor_sync(FULLMASK, rs0, 1);
    rs0 += __shfl_xor_sync(FULLMASK, rs0, 2);
    rs1 += __shfl_xor_sync(FULLMASK, rs1, 1);
    rs1 += __shfl_xor_sync(FULLMASK, rs1, 2);
    if (tq == 0) {
        ssum[half][m0 + gid]     = rs0;
        ssum[half][m0 + gid + 8] = rs1;
    }
    __syncthreads();
    if (tid < MT) sscale[tid] = 1.f / (ssum[0][tid] + ssum[1][tid]);
    __syncthreads();

    // segment-sum into fp (batch sorted -> run-flush), 2 cols per thread
    #pragma unroll
    for (int cc = 0; cc < 2; ++cc) {
        const int c = tid + cc * 256;
        float acc = 0.f;
        int prev = sbatch[0];
        for (int m = 0; m < valid; ++m) {
            int bb = sbatch[m];
            if (bb != prev) {
                atomicAdd(&fp[(size_t)prev * INNER + c], acc);
                acc = 0.f;
                prev = bb;
            }
            acc += ls[m * LSP + c] * sscale[m];
        }
        if (valid > 0) atomicAdd(&fp[(size_t)prev * INNER + c], acc);
    }
}

// ============================================================================
// Edge scatter: xB[dst] += x[src] (vec4 red), aggE[dst] += edge_attr[e]
// ============================================================================
__global__ void scatterK(const float* __restrict__ x,
                         const float* __restrict__ ea,
                         const int* __restrict__ ei,
                         float* __restrict__ xB, float* __restrict__ aggE,
                         int nEdges)
{
    long long gid = (long long)blockIdx.x * blockDim.x + threadIdx.x;
    int e = (int)(gid >> 4);
    int c = (int)(gid & 15);
    if (e >= nEdges) return;
    int src = __ldg(&ei[e]);
    int dst = __ldg(&ei[nEdges + e]);
    float4 g = ld4(&x[(size_t)src * XD + c * 4]);
    red_add_v4(&xB[(size_t)dst * XD + c * 4], g);
    if (c < 4) {
        float4 a = ld4(&ea[(size_t)e * ED + c * 4]);
        red_add_v4(&aggE[(size_t)dst * ED + c * 4], a);
    }
}

// ============================================================================
// Conv linear: x_new[n] = W_in @ concat(agg_x[n], agg_e[n]) + b (in-place xB)
// ============================================================================
__global__ void __launch_bounds__(256)
convLinear(float* __restrict__ xB, const float* __restrict__ aggE,
           const float* __restrict__ Wi, const float* __restrict__ bi, int nNodes)
{
    __shared__ float Wt[80 * 64];
    __shared__ float ax[4][80];
    const int tid = threadIdx.x;
    for (int i = tid; i < 64 * 80; i += 256) {
        int out = i / 80, k = i % 80;
        Wt[k * 64 + out] = Wi[i];
    }
    const int out = tid & 63, ng = tid >> 6;
    const int base = blockIdx.x * 16;
    for (int it = 0; it < 4; ++it) {
        int node = base + it * 4 + ng;
        __syncthreads();
        if (node < nNodes) {
            ax[ng][out] = xB[(size_t)node * XD + out];
            if (out < ED) ax[ng][64 + out] = aggE[(size_t)node * ED + out];
        }
        __syncthreads();
        if (node < nNodes) {
            float acc = bi[out];
            #pragma unroll
            for (int k = 0; k < 64; ++k) acc += Wt[k * 64 + out] * ax[ng][k];
            #pragma unroll
            for (int k = 0; k < 16; ++k) acc += Wt[(64 + k) * 64 + out] * ax[ng][64 + k];
            xB[(size_t)node * XD + out] = acc;
        }
    }
}

// ============================================================================
// Final MLP: out[g] = sigmoid( (fp[g] @ lin1^T + b1) @ lin2^T + b2 )
// ============================================================================
__global__ void finalK(const float* __restrict__ fp,
                       const float* __restrict__ l1w, const float* __restrict__ l1b,
                       const float* __restrict__ l2w, const float* __restrict__ l2b,
                       float* __restrict__ out, int nG)
{
    int warp = (int)((blockIdx.x * (long long)blockDim.x + threadIdx.x) >> 5);
    int lane = threadIdx.x & 31;
    if (warp >= nG) return;
    float f[16];
    #pragma unroll
    for (int j = 0; j < 16; ++j) f[j] = fp[(size_t)warp * INNER + lane + j * 32];
    float o2 = 0.f;
    for (int o = 0; o < 50; ++o) {
        float a = 0.f;
        #pragma unroll
        for (int j = 0; j < 16; ++j)
            a += f[j] * __ldg(&l1w[(size_t)o * INNER + lane + j * 32]);
        a += __shfl_xor_sync(FULLMASK, a, 16);
        a += __shfl_xor_sync(FULLMASK, a, 8);
        a += __shfl_xor_sync(FULLMASK, a, 4);
        a += __shfl_xor_sync(FULLMASK, a, 2);
        a += __shfl_xor_sync(FULLMASK, a, 1);
        if (lane == 0) o2 += (a + l1b[o]) * l2w[o];
    }
    if (lane == 0) {
        float z = o2 + l2b[0];
        out[warp] = 1.f / (1.f + __expf(-z));
    }
}

// ============================================================================
// Host orchestration (graph-capturable)
// ============================================================================
extern "C" void kernel_launch(void* const* d_in, const int* in_sizes, int n_in,
                              void* d_out, int out_size)
{
    const float* x_in  = (const float*)d_in[0];
    const float* eattr = (const float*)d_in[1];
    const float* Winw  = (const float*)d_in[2];
    const float* Winb  = (const float*)d_in[3];
    const float* Woutw = (const float*)d_in[4];
    const float* Woutb = (const float*)d_in[5];
    const float* l1w   = (const float*)d_in[6];
    const float* l1b   = (const float*)d_in[7];
    const float* l2w   = (const float*)d_in[8];
    const float* l2b   = (const float*)d_in[9];
    const int*   ei    = (const int*)d_in[10];
    const int*   batch = (const int*)d_in[11];

    const int nNodes = in_sizes[0] / XD;
    const int nEdges = in_sizes[1] / ED;
    const int nG     = out_size;

    float *x0, *x1, *aggE, *fp;
    cudaGetSymbolAddress((void**)&x0,   g_x0);
    cudaGetSymbolAddress((void**)&x1,   g_x1);
    cudaGetSymbolAddress((void**)&aggE, g_aggE);
    cudaGetSymbolAddress((void**)&fp,   g_fp);

    const int smemA = (MT * XP + 128 * XP + MT * LSP) * (int)sizeof(float); // 184320
    cudaFuncSetAttribute(kernelAmma, cudaFuncAttributeMaxDynamicSharedMemorySize, smemA);

    cudaMemsetAsync(fp, 0, (size_t)nG * INNER * sizeof(float));

    const int gridA    = (nNodes + MT - 1) / MT;
    const int gridScat = (int)(((long long)nEdges * 16 + 255) / 256);
    const int gridConv = (nNodes + 15) / 16;

    const float* cur = x_in;
    float* bufs[2] = { x0, x1 };
    int pb = 0;

    for (int i = 0; i <= DEPTH; ++i) {
        kernelAmma<<<gridA, 256, smemA>>>(cur, Woutw, Woutb, batch, fp, nNodes);
        if (i < DEPTH) {
            float* nxt = bufs[pb];
            cudaMemcpyAsync(nxt, cur, (size_t)nNodes * XD * sizeof(float),
                            cudaMemcpyDeviceToDevice);
            cudaMemsetAsync(aggE, 0, (size_t)nNodes * ED * sizeof(float));
            scatterK<<<gridScat, 256>>>(cur, eattr, ei, nxt, aggE, nEdges);
            convLinear<<<gridConv, 256>>>(nxt, aggE, Winw, Winb, nNodes);
            cur = nxt;
            pb ^= 1;
        }
    }

    finalK<<<(nG * 32 + 255) / 256, 256>>>(fp, l1w, l1b, l2w, l2b,
                                           (float*)d_out, nG);
}

// round 5
// speedup vs baseline: 3.3949x; 2.4446x over previous
#include <cuda_runtime.h>
#include <cuda_bf16.h>
#include <cstdint>

// Problem constants (shapes fixed by the dataset)
#define NN 500000
#define EE 4000000
#define GG 16384
#define XD 64
#define ED 16
#define INNER 512
#define DEPTH 4

#define FULLMASK 0xffffffffu

// ---------------- scratch (static device allocations; no cudaMalloc) -------
__device__ float g_x0[(size_t)NN * XD];
__device__ float g_x1[(size_t)NN * XD];
__device__ float g_aggE[(size_t)NN * ED];
__device__ float g_fp[(size_t)GG * INNER];
__device__ int   g_deg[NN];
__device__ int   g_rowptr[NN + 1];
__device__ int   g_cursor[NN];
__device__ int   g_bsum[512];
__device__ int   g_psrc[EE];
__device__ int   g_peid[EE];

// ---------------- helpers ----------------
__device__ __forceinline__ float4 ld4(const float* p) {
    return *reinterpret_cast<const float4*>(p);
}
__device__ __forceinline__ float2 ld2(const float* p) {
    return *reinterpret_cast<const float2*>(p);
}
__device__ __forceinline__ float to_tf32(float f) {
    uint32_t o;
    asm("cvt.rna.tf32.f32 %0, %1;" : "=r"(o) : "f"(f));
    return __uint_as_float(o);
}

// ============================================================================
// kernelAmma: tf32 mma.sync GEMM (logits = x @ W_out^T + b), fused
// softmax (no-max, clamped) + sorted-batch segment-sum into fp.
// smem: Wc fp32 [128][68] | ls bf16 [64][520] (x-stage overlapped with ls).
// Dynamic smem = 101376 B -> 2 CTAs/SM.
// ============================================================================
#define MT 64
#define LSPB 520   // bf16 elems per ls row (pad -> conflict-free epilogue stores)
#define XP 68

__global__ void __launch_bounds__(256, 2)
kernelAmma(const float* __restrict__ x, const float* __restrict__ W,
           const float* __restrict__ bias, const int* __restrict__ batch,
           float* __restrict__ fp, int nNodes)
{
    extern __shared__ char dsm[];
    float* Wc = (float*)dsm;                                   // 128*68*4 = 34816
    __nv_bfloat16* ls = (__nv_bfloat16*)(dsm + 34816);         // 64*520*2 = 66560
    float* xs = (float*)(dsm + 34816);                         // 17408 (dead after A-frag load)
    __shared__ float sbias[INNER];
    __shared__ float ssum[2][MT];
    __shared__ float sscale[MT];
    __shared__ int   sbatch[MT];

    const int tid  = threadIdx.x;
    const int w    = tid >> 5, lane = tid & 31;
    const int gid  = lane >> 2, tq = lane & 3;
    const int base = blockIdx.x * MT;
    const int valid = min(MT, nNodes - base);

    for (int i = tid; i < INNER; i += 256) sbias[i] = bias[i];
    if (tid < MT) sbatch[tid] = (tid < valid) ? batch[base + tid] : -1;

    // stage x tile (tf32-rounded): 64 rows x 16 float4
    for (int i = tid; i < MT * 16; i += 256) {
        int r = i >> 4, kq = i & 15;
        float4 v = (r < valid) ? ld4(&x[(size_t)(base + r) * XD + kq * 4])
                               : make_float4(0.f, 0.f, 0.f, 0.f);
        v.x = to_tf32(v.x); v.y = to_tf32(v.y); v.z = to_tf32(v.z); v.w = to_tf32(v.w);
        *(float4*)&xs[r * XP + kq * 4] = v;
    }
    __syncthreads();

    const int mt = w & 3, half = w >> 2;
    const int m0 = mt * 16;

    // A fragments (per-warp, reused across all 4 passes): 8 k-steps x 4 regs
    uint32_t A[8][4];
    {
        const uint32_t* xr = (const uint32_t*)xs;
        #pragma unroll
        for (int ks = 0; ks < 8; ++ks) {
            int c0 = ks * 8 + tq;
            A[ks][0] = xr[(m0 + gid) * XP + c0];
            A[ks][1] = xr[(m0 + gid + 8) * XP + c0];
            A[ks][2] = xr[(m0 + gid) * XP + c0 + 4];
            A[ks][3] = xr[(m0 + gid + 8) * XP + c0 + 4];
        }
    }

    float rs0 = 0.f, rs1 = 0.f;   // row sums for rows m0+gid and m0+gid+8

    for (int p = 0; p < 4; ++p) {
        __syncthreads();   // all A-frags loaded (p=0) / prior pass done with Wc
        // stage W rows [p*128, p*128+128) x 64 cols (tf32-rounded)
        for (int i = tid; i < 128 * 16; i += 256) {
            int n = i >> 4, kq = i & 15;
            float4 v = ld4(&W[(size_t)(p * 128 + n) * XD + kq * 4]);
            v.x = to_tf32(v.x); v.y = to_tf32(v.y); v.z = to_tf32(v.z); v.w = to_tf32(v.w);
            *(float4*)&Wc[n * XP + kq * 4] = v;
        }
        __syncthreads();

        const int cb = p * 128 + half * 64;
        const uint32_t* wr = (const uint32_t*)Wc;

        #pragma unroll
        for (int nt = 0; nt < 8; ++nt) {
            const int nloc = half * 64 + nt * 8 + gid;
            float d0 = 0.f, d1 = 0.f, d2 = 0.f, d3 = 0.f;
            #pragma unroll
            for (int ks = 0; ks < 8; ++ks) {
                uint32_t b0 = wr[nloc * XP + ks * 8 + tq];
                uint32_t b1 = wr[nloc * XP + ks * 8 + tq + 4];
                asm volatile(
                    "mma.sync.aligned.m16n8k8.row.col.f32.tf32.tf32.f32 "
                    "{%0,%1,%2,%3}, {%4,%5,%6,%7}, {%8,%9}, {%0,%1,%2,%3};"
                    : "+f"(d0), "+f"(d1), "+f"(d2), "+f"(d3)
                    : "r"(A[ks][0]), "r"(A[ks][1]), "r"(A[ks][2]), "r"(A[ks][3]),
                      "r"(b0), "r"(b1));
            }
            // fused epilogue: +bias, exp (clamped), row-sum, bf16 store once
            const int c = cb + nt * 8 + tq * 2;
            float e0 = __expf(fminf(d0 + sbias[c],     85.f));
            float e1 = __expf(fminf(d1 + sbias[c + 1], 85.f));
            float e2 = __expf(fminf(d2 + sbias[c],     85.f));
            float e3 = __expf(fminf(d3 + sbias[c + 1], 85.f));
            rs0 += e0 + e1;
            rs1 += e2 + e3;
            const int r0 = m0 + gid, r1 = r0 + 8;
            *(__nv_bfloat162*)&ls[r0 * LSPB + c] = __floats2bfloat162_rn(e0, e1);
            *(__nv_bfloat162*)&ls[r1 * LSPB + c] = __floats2bfloat162_rn(e2, e3);
        }
    }

    // reduce row sums across the 4-thread quad
    rs0 += __shfl_xor_sync(FULLMASK, rs0, 1);
    rs0 += __shfl_xor_sync(FULLMASK, rs0, 2);
    rs1 += __shfl_xor_sync(FULLMASK, rs1, 1);
    rs1 += __shfl_xor_sync(FULLMASK, rs1, 2);
    if (tq == 0) {
        ssum[half][m0 + gid]     = rs0;
        ssum[half][m0 + gid + 8] = rs1;
    }
    __syncthreads();
    if (tid < MT) sscale[tid] = 1.f / (ssum[0][tid] + ssum[1][tid]);
    __syncthreads();

    // segment-sum into fp (batch sorted -> run-flush), 2 cols per thread
    #pragma unroll
    for (int cc = 0; cc < 2; ++cc) {
        const int c = tid + cc * 256;
        float acc = 0.f;
        int prev = sbatch[0];
        for (int m = 0; m < valid; ++m) {
            int bb = sbatch[m];
            if (bb != prev) {
                atomicAdd(&fp[(size_t)prev * INNER + c], acc);
                acc = 0.f;
                prev = bb;
            }
            acc += __bfloat162float(ls[m * LSPB + c]) * sscale[m];
        }
        if (valid > 0) atomicAdd(&fp[(size_t)prev * INNER + c], acc);
    }
}

// ============================================================================
// CSR-by-dst build (edge_index constant within a call): count, scan, fill.
// ============================================================================
__global__ void countK(const int* __restrict__ ei, int* __restrict__ deg, int nE) {
    int e = blockIdx.x * 256 + threadIdx.x;
    if (e < nE) atomicAdd(&deg[ei[nE + e]], 1);
}

__global__ void scan1K(const int* __restrict__ deg, int* __restrict__ rowptr,
                       int* __restrict__ bsum, int n)
{
    __shared__ int wsum[8], woff[8];
    const int t = threadIdx.x;
    const int base = blockIdx.x * 2048 + t * 8;
    int v[8], s = 0;
    #pragma unroll
    for (int j = 0; j < 8; ++j) {
        int idx = base + j;
        v[j] = (idx < n) ? deg[idx] : 0;
        s += v[j];
    }
    const int lane = t & 31, wid = t >> 5;
    int sc = s;
    #pragma unroll
    for (int o = 1; o < 32; o <<= 1) {
        int u = __shfl_up_sync(FULLMASK, sc, o);
        if (lane >= o) sc += u;
    }
    if (lane == 31) wsum[wid] = sc;
    __syncthreads();
    if (t == 0) {
        int run = 0;
        #pragma unroll
        for (int i = 0; i < 8; ++i) { woff[i] = run; run += wsum[i]; }
        bsum[blockIdx.x] = run;
    }
    __syncthreads();
    int run = woff[wid] + sc - s;     // exclusive prefix for this thread
    #pragma unroll
    for (int j = 0; j < 8; ++j) {
        int idx = base + j;
        if (idx < n) rowptr[idx] = run;
        run += v[j];
    }
}

__global__ void scan2K(int* __restrict__ bsum, int nb) {
    __shared__ int wsum[8], woff[8];
    const int t = threadIdx.x;
    int v = (t < nb) ? bsum[t] : 0;
    const int lane = t & 31, wid = t >> 5;
    int sc = v;
    #pragma unroll
    for (int o = 1; o < 32; o <<= 1) {
        int u = __shfl_up_sync(FULLMASK, sc, o);
        if (lane >= o) sc += u;
    }
    if (lane == 31) wsum[wid] = sc;
    __syncthreads();
    if (t == 0) {
        int run = 0;
        #pragma unroll
        for (int i = 0; i < 8; ++i) { woff[i] = run; run += wsum[i]; }
    }
    __syncthreads();
    if (t < nb) bsum[t] = woff[wid] + sc - v;
}

__global__ void scan3K(int* __restrict__ rowptr, const int* __restrict__ bsum,
                       int n, int nE) {
    int i = blockIdx.x * 256 + threadIdx.x;
    if (i < n) rowptr[i] += bsum[i >> 11];
    if (i == 0) rowptr[n] = nE;
}

__global__ void fillK(const int* __restrict__ ei, int* __restrict__ cursor,
                      int* __restrict__ psrc, int* __restrict__ peid, int nE) {
    int e = blockIdx.x * 256 + threadIdx.x;
    if (e < nE) {
        int dst = ei[nE + e];
        int p = atomicAdd(&cursor[dst], 1);
        psrc[p] = ei[e];
        peid[p] = e;
    }
}

// ============================================================================
// aggEK: aggE[n] = sum of edge_attr over CSR list (constant across conv iters,
// computed ONCE per call). 16 lanes per node, 2 nodes per warp.
// ============================================================================
__global__ void __launch_bounds__(256) aggEK(
    const float* __restrict__ ea, const int* __restrict__ rowptr,
    const int* __restrict__ peid, float* __restrict__ aggE, int n)
{
    int warp = (blockIdx.x * 256 + threadIdx.x) >> 5;
    int lane = threadIdx.x & 31;
    int node = warp * 2 + (lane >> 4);
    int l16 = lane & 15;
    if (node >= n) return;
    int r = rowptr[node], re = rowptr[node + 1];
    float acc = 0.f, acc2 = 0.f;
    for (; r + 2 <= re; r += 2) {
        int e0 = peid[r], e1 = peid[r + 1];
        acc  += ea[(size_t)e0 * ED + l16];
        acc2 += ea[(size_t)e1 * ED + l16];
    }
    if (r < re) acc += ea[(size_t)peid[r] * ED + l16];
    aggE[(size_t)node * ED + l16] = acc + acc2;
}

// ============================================================================
// convK: fused gather + self-loop + linear.
// x_new[n] = W_in @ concat(x[n] + sum_{e:dst=n} x[src_e], aggE[n]) + b
// 1 warp handles 8 nodes (4 pairs); W staged once/block, amortized over pairs.
// ============================================================================
__global__ void __launch_bounds__(256) convK(
    const float* __restrict__ xin, const float* __restrict__ aggE,
    const int* __restrict__ rowptr, const int* __restrict__ psrc,
    const float* __restrict__ Wi, const float* __restrict__ bi,
    float* __restrict__ xout, int nNodes)
{
    __shared__ float Wt2[80 * 64];   // [k][2j]=Wi[j][k], [k][2j+1]=Wi[j+32][k]
    __shared__ float sb[64];
    __shared__ float aggA[8][80];
    __shared__ float aggB[8][80];
    const int tid = threadIdx.x, w = tid >> 5, lane = tid & 31;

    for (int i = tid; i < 80 * 64; i += 256) {
        int k = i >> 6, jj = i & 63;
        int j = (jj >> 1) + (jj & 1) * 32;
        Wt2[i] = Wi[j * 80 + k];
    }
    if (tid < 64) sb[tid] = bi[tid];
    __syncthreads();

    const int nbase = blockIdx.x * 64 + w * 8;
    for (int it = 0; it < 4; ++it) {
        const int na = nbase + it * 2;
        const int nb2 = na + 1;
        if (na >= nNodes) break;            // warp-uniform
        const bool vb = nb2 < nNodes;

        float2 accA = ld2(&xin[(size_t)na * XD + lane * 2]);   // self loop
        {
            int r = rowptr[na], re = rowptr[na + 1];
            for (; r + 2 <= re; r += 2) {
                int s0 = psrc[r], s1 = psrc[r + 1];
                float2 v0 = ld2(&xin[(size_t)s0 * XD + lane * 2]);
                float2 v1 = ld2(&xin[(size_t)s1 * XD + lane * 2]);
                accA.x += v0.x + v1.x; accA.y += v0.y + v1.y;
            }
            if (r < re) {
                float2 v = ld2(&xin[(size_t)psrc[r] * XD + lane * 2]);
                accA.x += v.x; accA.y += v.y;
            }
        }
        float2 accB = make_float2(0.f, 0.f);
        if (vb) {
            accB = ld2(&xin[(size_t)nb2 * XD + lane * 2]);
            int r = rowptr[nb2], re = rowptr[nb2 + 1];
            for (; r + 2 <= re; r += 2) {
                int s0 = psrc[r], s1 = psrc[r + 1];
                float2 v0 = ld2(&xin[(size_t)s0 * XD + lane * 2]);
                float2 v1 = ld2(&xin[(size_t)s1 * XD + lane * 2]);
                accB.x += v0.x + v1.x; accB.y += v0.y + v1.y;
            }
            if (r < re) {
                float2 v = ld2(&xin[(size_t)psrc[r] * XD + lane * 2]);
                accB.x += v.x; accB.y += v.y;
            }
        }
        *(float2*)&aggA[w][lane * 2] = accA;
        *(float2*)&aggB[w][lane * 2] = accB;
        if (lane < 16) {
            aggA[w][64 + lane] = aggE[(size_t)na * ED + lane];
            aggB[w][64 + lane] = vb ? aggE[(size_t)nb2 * ED + lane] : 0.f;
        }
        __syncwarp();

        float o0a = sb[lane], o1a = sb[lane + 32];
        float o0b = o0a, o1b = o1a;
        #pragma unroll
        for (int k = 0; k < 80; ++k) {
            float2 wt = *(const float2*)&Wt2[k * 64 + lane * 2];
            float a = aggA[w][k], b = aggB[w][k];
            o0a += wt.x * a; o1a += wt.y * a;
            o0b += wt.x * b; o1b += wt.y * b;
        }
        xout[(size_t)na * XD + lane]      = o0a;
        xout[(size_t)na * XD + lane + 32] = o1a;
        if (vb) {
            xout[(size_t)nb2 * XD + lane]      = o0b;
            xout[(size_t)nb2 * XD + lane + 32] = o1b;
        }
        __syncwarp();
    }
}

// ============================================================================
// Final MLP: out[g] = sigmoid( (fp[g] @ lin1^T + b1) @ lin2^T + b2 )
// ============================================================================
__global__ void finalK(const float* __restrict__ fp,
                       const float* __restrict__ l1w, const float* __restrict__ l1b,
                       const float* __restrict__ l2w, const float* __restrict__ l2b,
                       float* __restrict__ out, int nG)
{
    int warp = (int)((blockIdx.x * (long long)blockDim.x + threadIdx.x) >> 5);
    int lane = threadIdx.x & 31;
    if (warp >= nG) return;
    float f[16];
    #pragma unroll
    for (int j = 0; j < 16; ++j) f[j] = fp[(size_t)warp * INNER + lane + j * 32];
    float o2 = 0.f;
    for (int o = 0; o < 50; ++o) {
        float a = 0.f;
        #pragma unroll
        for (int j = 0; j < 16; ++j)
            a += f[j] * __ldg(&l1w[(size_t)o * INNER + lane + j * 32]);
        a += __shfl_xor_sync(FULLMASK, a, 16);
        a += __shfl_xor_sync(FULLMASK, a, 8);
        a += __shfl_xor_sync(FULLMASK, a, 4);
        a += __shfl_xor_sync(FULLMASK, a, 2);
        a += __shfl_xor_sync(FULLMASK, a, 1);
        if (lane == 0) o2 += (a + l1b[o]) * l2w[o];
    }
    if (lane == 0) {
        float z = o2 + l2b[0];
        out[warp] = 1.f / (1.f + __expf(-z));
    }
}

// ============================================================================
// Host orchestration (graph-capturable)
// ============================================================================
extern "C" void kernel_launch(void* const* d_in, const int* in_sizes, int n_in,
                              void* d_out, int out_size)
{
    const float* x_in  = (const float*)d_in[0];
    const float* eattr = (const float*)d_in[1];
    const float* Winw  = (const float*)d_in[2];
    const float* Winb  = (const float*)d_in[3];
    const float* Woutw = (const float*)d_in[4];
    const float* Woutb = (const float*)d_in[5];
    const float* l1w   = (const float*)d_in[6];
    const float* l1b   = (const float*)d_in[7];
    const float* l2w   = (const float*)d_in[8];
    const float* l2b   = (const float*)d_in[9];
    const int*   ei    = (const int*)d_in[10];
    const int*   batch = (const int*)d_in[11];

    const int nNodes = in_sizes[0] / XD;
    const int nEdges = in_sizes[1] / ED;
    const int nG     = out_size;

    float *x0, *x1, *aggE, *fp;
    int *deg, *rowptr, *cursor, *bsum, *psrc, *peid;
    cudaGetSymbolAddress((void**)&x0,     g_x0);
    cudaGetSymbolAddress((void**)&x1,     g_x1);
    cudaGetSymbolAddress((void**)&aggE,   g_aggE);
    cudaGetSymbolAddress((void**)&fp,     g_fp);
    cudaGetSymbolAddress((void**)&deg,    g_deg);
    cudaGetSymbolAddress((void**)&rowptr, g_rowptr);
    cudaGetSymbolAddress((void**)&cursor, g_cursor);
    cudaGetSymbolAddress((void**)&bsum,   g_bsum);
    cudaGetSymbolAddress((void**)&psrc,   g_psrc);
    cudaGetSymbolAddress((void**)&peid,   g_peid);

    const int smemA = 34816 + 66560;   // Wc fp32 + ls bf16 = 101376
    cudaFuncSetAttribute(kernelAmma, cudaFuncAttributeMaxDynamicSharedMemorySize, smemA);

    cudaMemsetAsync(fp, 0, (size_t)nG * INNER * sizeof(float));
    cudaMemsetAsync(deg, 0, (size_t)nNodes * sizeof(int));

    // ---- CSR build (once per call) ----
    const int gridE = (nEdges + 255) / 256;
    const int nb    = (nNodes + 2047) / 2048;
    countK<<<gridE, 256>>>(ei, deg, nEdges);
    scan1K<<<nb, 256>>>(deg, rowptr, bsum, nNodes);
    scan2K<<<1, 256>>>(bsum, nb);
    scan3K<<<(nNodes + 255) / 256, 256>>>(rowptr, bsum, nNodes, nEdges);
    cudaMemcpyAsync(cursor, rowptr, (size_t)nNodes * sizeof(int),
                    cudaMemcpyDeviceToDevice);
    fillK<<<gridE, 256>>>(ei, cursor, psrc, peid, nEdges);
    aggEK<<<((nNodes + 1) / 2 * 32 + 255) / 256, 256>>>(eattr, rowptr, peid, aggE, nNodes);

    const int gridA    = (nNodes + MT - 1) / MT;
    const int gridConv = (nNodes + 63) / 64;

    const float* cur = x_in;
    float* bufs[2] = { x0, x1 };
    int pb = 0;

    for (int i = 0; i <= DEPTH; ++i) {
        kernelAmma<<<gridA, 256, smemA>>>(cur, Woutw, Woutb, batch, fp, nNodes);
        if (i < DEPTH) {
            float* nxt = bufs[pb];
            convK<<<gridConv, 256>>>(cur, aggE, rowptr, psrc, Winw, Winb, nxt, nNodes);
            cur = nxt;
            pb ^= 1;
        }
    }

    finalK<<<(nG * 32 + 255) / 256, 256>>>(fp, l1w, l1b, l2w, l2b,
                                           (float*)d_out, nG);
}